// round 17
// baseline (speedup 1.0000x reference)
#include <cuda_runtime.h>
#include <cstdint>
#include <cstddef>

#define B_   128
#define T_   512
#define H_   256
#define G4_  1024

// recurrence geometry: 8 independent groups x 16 CTAs, 16 rows/group, 16 h-cols/CTA
#define NG       8
#define GRP_CTAS 16
#define HSTR     258
// smem: Us2 [256k][16j] ulonglong2 = 64KB | hs2 u64[16][258] = 32.25KB | P [8w][8r][16j] u128 = 16KB | base
#define OFF_HS   65536
#define OFF_P    (OFF_HS + 16*HSTR*8)
#define OFF_BASE (OFF_P + 8*8*16*16)
#define REC_SMEM (OFF_BASE + 16)

// ---------------- scratch (device globals; no allocation allowed) ----------------
__device__ float g_xz[(size_t)B_ * T_ * G4_];    // gate pre-activations (reused per layer)
__device__ float g_hseq[(size_t)B_ * T_ * H_];   // hidden sequence (layer0 then layer1; flag-ordered aliasing)
__device__ float g_dense[(size_t)B_ * T_ * H_];  // dense(tanh) output, consumed by LN
__device__ unsigned long long g_arrive[NG * 16];     // padded per-group counters
__device__ unsigned long long g_release[NG * 16];
__device__ unsigned int g_tileflag[4096];        // per-GEMM-tile monotonic flags (shared by both layers)

// ---------------- packed f32x2 helpers (sm_103a FFMA2) ----------------
static __device__ __forceinline__ unsigned long long f2pack(float a, float b) {
    unsigned long long r;
    asm("mov.b64 %0, {%1, %2};" : "=l"(r) : "r"(__float_as_uint(a)), "r"(__float_as_uint(b)));
    return r;
}
static __device__ __forceinline__ void f2unpack(unsigned long long v, float& a, float& b) {
    unsigned int x, y;
    asm("mov.b64 {%0, %1}, %2;" : "=r"(x), "=r"(y) : "l"(v));
    a = __uint_as_float(x); b = __uint_as_float(y);
}
static __device__ __forceinline__ unsigned long long f2fma(
    unsigned long long a, unsigned long long b, unsigned long long c) {
    unsigned long long d;
    asm("fma.rn.f32x2 %0, %1, %2, %3;" : "=l"(d) : "l"(a), "l"(b), "l"(c));
    return d;
}
static __device__ __forceinline__ unsigned long long f2add(
    unsigned long long a, unsigned long long b) {
    unsigned long long d;
    asm("add.rn.f32x2 %0, %1, %2;" : "=l"(d) : "l"(a), "l"(b));
    return d;
}

// fast activations (rel err ~1e-6; tolerance 1e-3)
static __device__ __forceinline__ float sig_f(float x) {
    return __fdividef(1.f, 1.f + __expf(-x));
}
static __device__ __forceinline__ float tanh_f(float x) {
    return __fdividef(2.f, 1.f + __expf(-2.f * x)) - 1.f;
}

// ---------------- per-group barrier (16 CTAs; groups independent) ----------------
static __device__ __forceinline__ void gsync(int grp, unsigned long long& phase) {
    __threadfence();
    __syncthreads();
    if (threadIdx.x == 0) {
        unsigned long long old = atomicAdd(&g_arrive[grp * 16], 1ULL);
        if (old == phase * GRP_CTAS + (GRP_CTAS - 1)) {
            __threadfence();
            *(volatile unsigned long long*)&g_release[grp * 16] = phase + 1;
        } else {
            while (*(volatile unsigned long long*)&g_release[grp * 16] <= phase) { }
        }
        phase++;
    }
    __syncthreads();
}

// ---------------- shared GEMM-tile core (BM=128, BN=128, BK=16, 8x8/thread) ----------------
// As2/Bs live in dynamic smem at sraw. ldA/ldB/ldC are row strides (floats).
template <bool TANH>
static __device__ __forceinline__ void gemm_tile(
    unsigned char* sraw, const float* __restrict__ A, const float* __restrict__ W,
    const float* __restrict__ bias, float* __restrict__ C,
    int m0, int n0, int ldB, int tid)
{
    unsigned long long (*As2)[130] = (unsigned long long (*)[130])sraw;
    float (*Bs)[132] = (float (*)[132])(sraw + 16 * 130 * 8);
    const int tr = tid >> 4;
    const int tc = tid & 15;

    unsigned long long acc[8][4];
#pragma unroll
    for (int i = 0; i < 8; i++)
#pragma unroll
        for (int p = 0; p < 4; p++) acc[i][p] = 0ULL;

    for (int k0 = 0; k0 < 256; k0 += 16) {
#pragma unroll
        for (int s = 0; s < 2; s++) {
            int e = tid + s * 256;
            int row = e >> 2, q = e & 3;
            float4 v = *(const float4*)&A[(size_t)(m0 + row) * 256 + k0 + q * 4];
            As2[q * 4 + 0][row] = f2pack(v.x, v.x);
            As2[q * 4 + 1][row] = f2pack(v.y, v.y);
            As2[q * 4 + 2][row] = f2pack(v.z, v.z);
            As2[q * 4 + 3][row] = f2pack(v.w, v.w);
        }
#pragma unroll
        for (int s = 0; s < 2; s++) {
            int e = tid + s * 256;
            int krow = e >> 5, nq = e & 31;
            *(float4*)&Bs[krow][nq * 4] =
                *(const float4*)&W[(size_t)(k0 + krow) * ldB + n0 + nq * 4];
        }
        __syncthreads();
#pragma unroll
        for (int kk = 0; kk < 16; kk++) {
            ulonglong2 a0 = *(const ulonglong2*)&As2[kk][tr * 8 + 0];
            ulonglong2 a1 = *(const ulonglong2*)&As2[kk][tr * 8 + 2];
            ulonglong2 a2 = *(const ulonglong2*)&As2[kk][tr * 8 + 4];
            ulonglong2 a3 = *(const ulonglong2*)&As2[kk][tr * 8 + 6];
            ulonglong2 b0 = *(const ulonglong2*)&Bs[kk][tc * 8 + 0];
            ulonglong2 b1 = *(const ulonglong2*)&Bs[kk][tc * 8 + 4];
            unsigned long long ap[8] = {a0.x, a0.y, a1.x, a1.y, a2.x, a2.y, a3.x, a3.y};
            unsigned long long bp[4] = {b0.x, b0.y, b1.x, b1.y};
#pragma unroll
            for (int i = 0; i < 8; i++)
#pragma unroll
                for (int p = 0; p < 4; p++)
                    acc[i][p] = f2fma(ap[i], bp[p], acc[i][p]);
        }
        __syncthreads();
    }

    float4 bv0 = *(const float4*)&bias[n0 + tc * 8];
    float4 bv1 = *(const float4*)&bias[n0 + tc * 8 + 4];
#pragma unroll
    for (int i = 0; i < 8; i++) {
        float c0, c1, c2, c3, c4, c5, c6, c7;
        f2unpack(acc[i][0], c0, c1);
        f2unpack(acc[i][1], c2, c3);
        f2unpack(acc[i][2], c4, c5);
        f2unpack(acc[i][3], c6, c7);
        c0 += bv0.x; c1 += bv0.y; c2 += bv0.z; c3 += bv0.w;
        c4 += bv1.x; c5 += bv1.y; c6 += bv1.z; c7 += bv1.w;
        if (TANH) {
            c0 = tanh_f(c0); c1 = tanh_f(c1); c2 = tanh_f(c2); c3 = tanh_f(c3);
            c4 = tanh_f(c4); c5 = tanh_f(c5); c6 = tanh_f(c6); c7 = tanh_f(c7);
        }
        float* cp = &C[(size_t)(m0 + tr * 8 + i) * ldB + n0 + tc * 8];
        *(float4*)cp = make_float4(c0, c1, c2, c3);
        *(float4*)(cp + 4) = make_float4(c4, c5, c6, c7);
    }
}

// ================= fused layer: rec CTAs + chasing xz-GEMM CTAs (+ chasing dense CTAs) =================
template <bool DENSE>
__global__ __launch_bounds__(256, 2) void fused_layer(
    const float* __restrict__ A, const float* __restrict__ W, const float* __restrict__ bias,
    const float* __restrict__ U, float* __restrict__ xz, float* __restrict__ hseq,
    const float* __restrict__ Wd, const float* __restrict__ bd, float* __restrict__ dense_out)
{
    extern __shared__ unsigned char sraw[];
    const int tid = threadIdx.x;

    if (DENSE && blockIdx.x >= 128 + 4096) {
        // ---------------- dense tile CTA: chases this layer's recurrence via g_release ----------------
        const int d = blockIdx.x - (128 + 4096);
        const int dn = d & 1;
        const int dm = d >> 1;
        const int m0 = dm * 128;           // m = r*512 + t
        const int n0 = dn * 128;
        const int rrow = dm >> 2;          // batch row
        const int tb1 = (dm & 3) + 1;      // t-blocks of h needed
        const int grp = rrow >> 4;
        if (tid == 0) {
            unsigned long long C = *(volatile unsigned long long*)&g_release[grp * 16];
            // layer-1 start phase P0 = 1024i+512; C in [P0, P0+512] -> recover P0 exactly
            unsigned long long P0 = ((C - 512ULL) / 1024ULL) * 1024ULL + 512ULL;
            unsigned long long tgt = P0 + (unsigned long long)(tb1 * 128);
            while (*(volatile unsigned long long*)&g_release[grp * 16] < tgt) { }
            __threadfence();
        }
        __syncthreads();
        gemm_tile<true>(sraw, hseq, Wd, bd, dense_out, m0, n0, H_, tid);
        return;
    }

    if (blockIdx.x >= 128) {
        // ---------------- xz-GEMM tile CTA ----------------
        const int g2 = blockIdx.x - 128;
        const int nb = g2 & 7;
        const int rm = (g2 >> 3) & 127;
        const int tb = g2 >> 10;
        gemm_tile<false>(sraw, A, W, bias, xz, rm * 512 + tb * 128, nb * 128, G4_, tid);
        __threadfence();
        __syncthreads();
        if (tid == 0) atomicAdd(&g_tileflag[g2], 1u);
        return;
    }

    // ---------------- recurrence CTA (R13 core + tile-flag chasing + two-pass P) ----------------
    ulonglong2* Us2 = (ulonglong2*)sraw;                             // [256 k][16 j]
    unsigned long long* hs2 = (unsigned long long*)(sraw + OFF_HS);  // [16 r][HSTR] (h,h)
    ulonglong2* P = (ulonglong2*)(sraw + OFF_P);                     // [8 w][8 r][16 j]
    unsigned int* sbase = (unsigned int*)(sraw + OFF_BASE);

    const int cta = blockIdx.x;
    const int grp = cta >> 4;            // 0..7
    const int slot = cta & 15;
    const int r0 = grp * 16;             // batch rows
    const int j0 = slot * 16;            // h columns
    const int wid = tid >> 5;
    const int lane = tid & 31;
    const int kbase = (tid >> 4) * 16;   // k-chunk base
    const int j = tid & 15;
    const int rr = tid >> 4;             // cell row 0..15
    const int jj = tid & 15;             // cell col 0..15

    // Load U slice once: Us2[k*16+j] = {(U[k][i],U[k][f]), (U[k][g],U[k][o])}
    for (int e = tid; e < 4096; e += 256) {
        int k = e >> 4, jx = e & 15;
        const float* up = U + (size_t)k * G4_ + j0 + jx;
        ulonglong2 v;
        v.x = f2pack(up[0], up[256]);
        v.y = f2pack(up[512], up[768]);
        Us2[e] = v;
    }
    for (int e = tid; e < 16 * HSTR; e += 256) hs2[e] = 0ULL;

    unsigned long long phase = 0;
    if (tid == 0) {
        phase = *(volatile unsigned long long*)&g_release[grp * 16];
        *sbase = (unsigned int)(phase / (unsigned long long)T_ + 1ULL);  // tile-flag target
    }
    __syncthreads();
    const unsigned int ftgt = *sbase;

    // wait for t-block 0 tiles of our 16 rows (128 flags, one per thread<128)
    {
        if (tid < 128) {
            const volatile unsigned int* fp = &g_tileflag[(r0 + (tid >> 3)) * 8 + (tid & 7)];
            while (*fp < ftgt) { }
            __threadfence();
        }
        __syncthreads();
    }

    // Prime xz for t=0
    float cz0, cz1, cz2, cz3;
    {
        const float* xp = xz + (size_t)(r0 + rr) * T_ * G4_ + j0 + jj;
        cz0 = __ldcs(xp);
        cz1 = __ldcs(xp + 256);
        cz2 = __ldcs(xp + 512);
        cz3 = __ldcs(xp + 768);
    }
    float c = 0.f;
    __syncthreads();

    const ulonglong2* up2 = Us2 + (size_t)kbase * 16 + j;
    const unsigned long long* hb = hs2 + kbase;

    for (int t = 0; t < T_; ++t) {
        // chase: before prefetching t+1, ensure its t-block tiles are published
        if (((t + 1) & 127) == 0 && t + 1 < T_) {
            int tb = (t + 1) >> 7;
            if (tid < 128) {
                const volatile unsigned int* fp =
                    &g_tileflag[tb * 1024 + (r0 + (tid >> 3)) * 8 + (tid & 7)];
                while (*fp < ftgt) { }
                __threadfence();
            }
            __syncthreads();
        }
        // Prefetch next step's xz
        float nz0 = 0.f, nz1 = 0.f, nz2 = 0.f, nz3 = 0.f;
        if (t + 1 < T_) {
            const float* xp = xz + ((size_t)(r0 + rr) * T_ + (t + 1)) * G4_ + j0 + jj;
            nz0 = __ldcs(xp);
            nz1 = __ldcs(xp + 256);
            nz2 = __ldcs(xp + 512);
            nz3 = __ldcs(xp + 768);
        }

        // FMA: 16 k x 16 rows; one U-quad read per k, reused across all 16 rows
        unsigned long long accA[16], accB[16];
#pragma unroll
        for (int r = 0; r < 16; r++) { accA[r] = 0ULL; accB[r] = 0ULL; }
#pragma unroll
        for (int kk = 0; kk < 16; kk += 2) {
            ulonglong2 u0 = up2[(size_t)kk * 16];
            ulonglong2 u1 = up2[(size_t)(kk + 1) * 16];
#pragma unroll
            for (int r = 0; r < 16; r++) {
                ulonglong2 h2 = *(const ulonglong2*)&hb[(size_t)r * HSTR + kk];  // broadcast
                accA[r] = f2fma(h2.x, u0.x, accA[r]);
                accB[r] = f2fma(h2.x, u0.y, accB[r]);
                accA[r] = f2fma(h2.y, u1.x, accA[r]);
                accB[r] = f2fma(h2.y, u1.y, accB[r]);
            }
        }
        // Stage 1: fold kc pairs (lane, lane+16)
#pragma unroll
        for (int r = 0; r < 16; r++) {
            accA[r] = f2add(accA[r], __shfl_down_sync(0xFFFFFFFFu, accA[r], 16));
            accB[r] = f2add(accB[r], __shfl_down_sync(0xFFFFFFFFu, accB[r], 16));
        }
        // Two-pass P reduction (halved P buffer)
        unsigned long long zA = 0ULL, zB = 0ULL;
        if (lane < 16) {
            ulonglong2* pw = P + (size_t)wid * 128 + lane;
#pragma unroll
            for (int r = 0; r < 8; r++)
                pw[(size_t)r * 16] = make_ulonglong2(accA[r], accB[r]);
        }
        __syncthreads();
        if (tid < 128) {
#pragma unroll
            for (int wv = 0; wv < 8; wv++) {
                ulonglong2 p = P[(size_t)wv * 128 + (rr & 7) * 16 + jj];
                zA = f2add(zA, p.x);
                zB = f2add(zB, p.y);
            }
        }
        __syncthreads();
        if (lane < 16) {
            ulonglong2* pw = P + (size_t)wid * 128 + lane;
#pragma unroll
            for (int r = 8; r < 16; r++)
                pw[(size_t)(r - 8) * 16] = make_ulonglong2(accA[r], accB[r]);
        }
        __syncthreads();
        if (tid >= 128) {
#pragma unroll
            for (int wv = 0; wv < 8; wv++) {
                ulonglong2 p = P[(size_t)wv * 128 + (rr & 7) * 16 + jj];
                zA = f2add(zA, p.x);
                zB = f2add(zB, p.y);
            }
        }
        // gates for cell (rr, jj)
        {
            float azi, azf, azg, azo;
            f2unpack(zA, azi, azf);
            f2unpack(zB, azg, azo);
            azi += cz0; azf += cz1; azg += cz2; azo += cz3;
            float ig = sig_f(azi);
            float fg = sig_f(azf);
            float gg = tanh_f(azg);
            float og = sig_f(azo);
            c = fg * c + ig * gg;
            float h = og * tanh_f(c);
            __stcg(&hseq[((size_t)(r0 + rr) * T_ + t) * H_ + j0 + jj], h);
        }
        cz0 = nz0; cz1 = nz1; cz2 = nz2; cz3 = nz3;

        gsync(grp, phase);   // h(t) visible group-wide

        // Refill duplicated h tile from L2-hot hseq[t]
        if (t + 1 < T_) {
#pragma unroll
            for (int i = 0; i < 4; i++) {
                int e = tid + i * 256;
                int rw = e >> 6, cc = (e & 63) * 4;
                float4 v = __ldcg((const float4*)&hseq[((size_t)(r0 + rw) * T_ + t) * H_ + cc]);
                unsigned long long* d = hs2 + (size_t)rw * HSTR + cc;
                d[0] = f2pack(v.x, v.x);
                d[1] = f2pack(v.y, v.y);
                d[2] = f2pack(v.z, v.z);
                d[3] = f2pack(v.w, v.w);
            }
            __syncthreads();
        }
    }
}

// ---------------- LayerNorm over last dim (256), one warp per row ----------------
__global__ __launch_bounds__(256) void ln_kernel(
    const float* __restrict__ X, const float* __restrict__ gamma,
    const float* __restrict__ beta, float* __restrict__ out)
{
    int w = threadIdx.x >> 5, lane = threadIdx.x & 31;
    size_t row = (size_t)blockIdx.x * 8 + w;
    const float* x = X + row * 256;
    float4 v0 = *(const float4*)&x[lane * 4];
    float4 v1 = *(const float4*)&x[128 + lane * 4];
    float s = v0.x + v0.y + v0.z + v0.w + v1.x + v1.y + v1.z + v1.w;
    float q = v0.x * v0.x + v0.y * v0.y + v0.z * v0.z + v0.w * v0.w
            + v1.x * v1.x + v1.y * v1.y + v1.z * v1.z + v1.w * v1.w;
#pragma unroll
    for (int o = 16; o > 0; o >>= 1) {
        s += __shfl_xor_sync(0xFFFFFFFFu, s, o);
        q += __shfl_xor_sync(0xFFFFFFFFu, q, o);
    }
    float mu = s * (1.f / 256.f);
    float var = q * (1.f / 256.f) - mu * mu;
    float rstd = rsqrtf(var + 1e-3f);
    float4 g0 = *(const float4*)&gamma[lane * 4];
    float4 g1 = *(const float4*)&gamma[128 + lane * 4];
    float4 e0 = *(const float4*)&beta[lane * 4];
    float4 e1 = *(const float4*)&beta[128 + lane * 4];
    float4 o0, o1;
    o0.x = (v0.x - mu) * rstd * g0.x + e0.x;
    o0.y = (v0.y - mu) * rstd * g0.y + e0.y;
    o0.z = (v0.z - mu) * rstd * g0.z + e0.z;
    o0.w = (v0.w - mu) * rstd * g0.w + e0.w;
    o1.x = (v1.x - mu) * rstd * g1.x + e1.x;
    o1.y = (v1.y - mu) * rstd * g1.y + e1.y;
    o1.z = (v1.z - mu) * rstd * g1.z + e1.z;
    o1.w = (v1.w - mu) * rstd * g1.w + e1.w;
    float* op = out + row * 256;
    *(float4*)&op[lane * 4] = o0;
    *(float4*)&op[128 + lane * 4] = o1;
}

// ---------------- entry point ----------------
extern "C" void kernel_launch(void* const* d_in, const int* in_sizes, int n_in,
                              void* d_out, int out_size)
{
    const float* x  = (const float*)d_in[0];
    const float* W0 = (const float*)d_in[1];
    const float* U0 = (const float*)d_in[2];
    const float* b0 = (const float*)d_in[3];
    const float* W1 = (const float*)d_in[4];
    const float* U1 = (const float*)d_in[5];
    const float* b1 = (const float*)d_in[6];
    const float* Wd = (const float*)d_in[7];
    const float* bd = (const float*)d_in[8];
    const float* ga = (const float*)d_in[9];
    const float* be = (const float*)d_in[10];
    float* out = (float*)d_out;

    float *xz, *hseq, *dns;
    cudaGetSymbolAddress((void**)&xz, g_xz);
    cudaGetSymbolAddress((void**)&hseq, g_hseq);
    cudaGetSymbolAddress((void**)&dns, g_dense);
    cudaFuncSetAttribute(fused_layer<false>, cudaFuncAttributeMaxDynamicSharedMemorySize, REC_SMEM);
    cudaFuncSetAttribute(fused_layer<true>, cudaFuncAttributeMaxDynamicSharedMemorySize, REC_SMEM);

    // Layer 0: GEMM chases into recurrence within one kernel
    fused_layer<false><<<128 + 4096, 256, REC_SMEM>>>(x, W0, b0, U0, xz, hseq,
                                                      nullptr, nullptr, nullptr);
    // Layer 1: xz-GEMM chases (reads h0 before rec overwrites with h1, flag-ordered)
    // + dense(tanh) tiles chase h1 production via the group release counters
    fused_layer<true><<<128 + 4096 + 1024, 256, REC_SMEM>>>(hseq, W1, b1, U1, xz, hseq,
                                                            Wd, bd, dns);
    // LayerNorm on dense output
    ln_kernel<<<8192, 256>>>(dns, ga, be, out);
}